// round 13
// baseline (speedup 1.0000x reference)
#include <cuda_runtime.h>
#include <cuda_bf16.h>

// db4 level-1 DWT low-pass reconstruction. 8 contiguous floats per thread via
// Blackwell 256-bit vector ld/st, distance-1 shuffle halos, no shared memory.
// All global loads (main LDG.256 + lane-0/31 edge patches) front-batched so
// patch latency overlaps main-load latency. Streaming (.cs) stores.
// x: [8192 rows, 4096] fp32. out = low (N floats) then high (N floats).
//
//   ca[K]     = sum_{m=0..7} h[m] * X(2K+1-m)     (X = symmetric-ext x)
//   low[2K]   = h1*ca[K] + h3*ca[K+1] + h5*ca[K+2] + h7*ca[K+3]
//   low[2K+1] = h0*ca[K] + h2*ca[K+1] + h4*ca[K+2] + h6*ca[K+3]
//   high      = x - low
//
// Thread t (256/CTA), group g in {0,1}: owns float8 E = 256*g + t ->
// outputs x[8E .. 8E+7]. Window w[0..19] = X(8E-6 .. 8E+13):
//   w6..w13  = own float8 (one LDG.256)
//   w0..w5   = lane t-1 floats 2..7  (6 x shfl_up 1)
//   w14..w19 = lane t+1 floats 0..5  (6 x shfl_down 1)
// Lanes 0/31 patch from global; row ends symmetric-reflect.

#define ROW_L    4096
#define NTHREADS 256
#define NF8      (ROW_L / 8)     // 512 float8 per row
#define NF4      (ROW_L / 4)

struct F8 { float v[8]; };

__device__ __forceinline__ F8 ldg256(const float* p) {
    F8 r;
    asm("ld.global.nc.v8.f32 {%0,%1,%2,%3,%4,%5,%6,%7}, [%8];"
        : "=f"(r.v[0]), "=f"(r.v[1]), "=f"(r.v[2]), "=f"(r.v[3]),
          "=f"(r.v[4]), "=f"(r.v[5]), "=f"(r.v[6]), "=f"(r.v[7])
        : "l"(p));
    return r;
}

__device__ __forceinline__ void stg256cs(float* p,
                                         float a0, float a1, float a2, float a3,
                                         float a4, float a5, float a6, float a7) {
    asm volatile("st.global.cs.v8.f32 [%0], {%1,%2,%3,%4,%5,%6,%7,%8};"
        :: "l"(p), "f"(a0), "f"(a1), "f"(a2), "f"(a3),
           "f"(a4), "f"(a5), "f"(a6), "f"(a7)
        : "memory");
}

__global__ void __launch_bounds__(NTHREADS)
dwt_db4_kernel(const float* __restrict__ x,
               float* __restrict__ low_out,
               float* __restrict__ high_out)
{
    const float h0 = -0.010597401784997278f;
    const float h1 =  0.032883011666982945f;
    const float h2 =  0.030841381835986965f;
    const float h3 = -0.18703481171888114f;
    const float h4 = -0.02798376941698385f;
    const float h5 =  0.6308807679295904f;
    const float h6 =  0.7148465705525415f;
    const float h7 =  0.23037781330885523f;

    const int t = threadIdx.x;
    const int l = t & 31;
    const size_t row = blockIdx.x;
    const float*  __restrict__ xr  = x + row * (size_t)ROW_L;
    const float4* __restrict__ xr4 = (const float4*)xr;
    float* __restrict__ lowp  = low_out  + row * (size_t)ROW_L;
    float* __restrict__ highp = high_out + row * (size_t)ROW_L;

    // ---- Front batch: ALL global loads issued back-to-back ----
    F8 va[2];
    #pragma unroll
    for (int g = 0; g < 2; ++g)
        va[g] = ldg256(xr + (size_t)(g * NTHREADS + t) * 8);

    // Edge-patch loads for lanes 0 / 31 (both groups), hoisted so their
    // latency overlaps the main loads instead of trailing the shuffles.
    float4 pa[2], pb[2];       // lane 0: A,B ; lane 31: C,D
    bool refl_lo[2], refl_hi[2];
    if (l == 0) {
        #pragma unroll
        for (int g = 0; g < 2; ++g) {
            const int E = g * NTHREADS + t;
            const bool refl = (E == 0);
            refl_lo[g] = refl;
            pa[g] = xr4[refl ? 1 : 2 * E - 2];
            pb[g] = xr4[refl ? 0 : 2 * E - 1];
        }
    }
    if (l == 31) {
        #pragma unroll
        for (int g = 0; g < 2; ++g) {
            const int E = g * NTHREADS + t;
            const bool refl = (E == NF8 - 1);
            refl_hi[g] = refl;
            pa[g] = xr4[refl ? (NF4 - 1) : 2 * E + 2];
            pb[g] = xr4[refl ? (NF4 - 2) : 2 * E + 3];
        }
    }

    #pragma unroll
    for (int g = 0; g < 2; ++g) {
        const F8 v = va[g];

        // window w[i] = X(8E - 6 + i), i = 0..19
        float w0, w1, w2, w3, w4, w5;
        const float w6 = v.v[0], w7 = v.v[1], w8 = v.v[2], w9 = v.v[3];
        const float w10 = v.v[4], w11 = v.v[5], w12 = v.v[6], w13 = v.v[7];
        float w14, w15, w16, w17, w18, w19;

        // halos via distance-1 shuffle (full-warp convergent)
        w0  = __shfl_up_sync(0xffffffffu, v.v[2], 1);
        w1  = __shfl_up_sync(0xffffffffu, v.v[3], 1);
        w2  = __shfl_up_sync(0xffffffffu, v.v[4], 1);
        w3  = __shfl_up_sync(0xffffffffu, v.v[5], 1);
        w4  = __shfl_up_sync(0xffffffffu, v.v[6], 1);
        w5  = __shfl_up_sync(0xffffffffu, v.v[7], 1);
        w14 = __shfl_down_sync(0xffffffffu, v.v[0], 1);
        w15 = __shfl_down_sync(0xffffffffu, v.v[1], 1);
        w16 = __shfl_down_sync(0xffffffffu, v.v[2], 1);
        w17 = __shfl_down_sync(0xffffffffu, v.v[3], 1);
        w18 = __shfl_down_sync(0xffffffffu, v.v[4], 1);
        w19 = __shfl_down_sync(0xffffffffu, v.v[5], 1);

        // apply pre-loaded edge patches
        if (l == 0) {
            const float4 A = pa[g], B = pb[g];
            if (refl_lo[g]) { w0 = A.y; w1 = A.x; w2 = B.w; w3 = B.z; w4 = B.y; w5 = B.x; }
            else            { w0 = A.z; w1 = A.w; w2 = B.x; w3 = B.y; w4 = B.z; w5 = B.w; }
        }
        if (l == 31) {
            const float4 C = pa[g], D = pb[g];
            if (refl_hi[g]) { w14 = C.w; w15 = C.z; w16 = C.y; w17 = C.x; w18 = D.w; w19 = D.z; }
            else            { w14 = C.x; w15 = C.y; w16 = C.z; w17 = C.w; w18 = D.x; w19 = D.y; }
        }

        // analysis: ca[j] (global coeff index 4E + j), j = 0..6
        // ca_j = sum_m h[m] * w[2j + 7 - m]
        const float wv[20] = { w0, w1, w2, w3, w4, w5, w6, w7, w8, w9,
                               w10, w11, w12, w13, w14, w15, w16, w17, w18, w19 };
        float ca[7];
        #pragma unroll
        for (int j = 0; j < 7; ++j) {
            float s;
            s = h0 * wv[2 * j + 7];
            s = fmaf(h1, wv[2 * j + 6], s);
            s = fmaf(h2, wv[2 * j + 5], s);
            s = fmaf(h3, wv[2 * j + 4], s);
            s = fmaf(h4, wv[2 * j + 3], s);
            s = fmaf(h5, wv[2 * j + 2], s);
            s = fmaf(h6, wv[2 * j + 1], s);
            s = fmaf(h7, wv[2 * j + 0], s);
            ca[j] = s;
        }

        // synthesis: pairs p = 0..3 -> outputs x[8E .. 8E+7]
        float le[4], lo[4];
        #pragma unroll
        for (int p = 0; p < 4; ++p) {
            float e;
            e = h1 * ca[p];
            e = fmaf(h3, ca[p + 1], e);
            e = fmaf(h5, ca[p + 2], e);
            e = fmaf(h7, ca[p + 3], e);
            le[p] = e;

            float o;
            o = h0 * ca[p];
            o = fmaf(h2, ca[p + 1], o);
            o = fmaf(h4, ca[p + 2], o);
            o = fmaf(h6, ca[p + 3], o);
            lo[p] = o;
        }

        const int E = g * NTHREADS + t;
        stg256cs(lowp + (size_t)E * 8,
                 le[0], lo[0], le[1], lo[1], le[2], lo[2], le[3], lo[3]);
        stg256cs(highp + (size_t)E * 8,
                 w6 - le[0], w7 - lo[0], w8 - le[1], w9 - lo[1],
                 w10 - le[2], w11 - lo[2], w12 - le[3], w13 - lo[3]);
    }
}

extern "C" void kernel_launch(void* const* d_in, const int* in_sizes, int n_in,
                              void* d_out, int out_size)
{
    const float* x = (const float*)d_in[0];
    const int n = in_sizes[0];            // 16*512*4096
    float* low  = (float*)d_out;          // outputs concatenated: (low, high)
    float* high = low + (size_t)n;
    const int rows = n / ROW_L;           // 8192
    dwt_db4_kernel<<<rows, NTHREADS>>>(x, low, high);
}

// round 14
// speedup vs baseline: 1.0010x; 1.0010x over previous
#include <cuda_runtime.h>
#include <cuda_bf16.h>

// db4 level-1 DWT low-pass reconstruction. 8 contiguous floats per thread via
// Blackwell 256-bit vector ld/st (ld.global.nc.v8.f32 / st.global.v8.f32),
// distance-1 shuffle halos, no shared memory, front-batched loads.
// In-group edge-patch loads issued BEFORE the shuffles so their L2 latency
// overlaps the shuffle sequence (no cross-group liveness -> regs stay 40).
// x: [8192 rows, 4096] fp32. out = low (N floats) then high (N floats).
//
//   ca[K]     = sum_{m=0..7} h[m] * X(2K+1-m)     (X = symmetric-ext x)
//   low[2K]   = h1*ca[K] + h3*ca[K+1] + h5*ca[K+2] + h7*ca[K+3]
//   low[2K+1] = h0*ca[K] + h2*ca[K+1] + h4*ca[K+2] + h6*ca[K+3]
//   high      = x - low
//
// Thread t (256/CTA), group g in {0,1}: owns float8 E = 256*g + t ->
// outputs x[8E .. 8E+7]. Window w[0..19] = X(8E-6 .. 8E+13):
//   w6..w13  = own float8 (one LDG.256)
//   w0..w5   = lane t-1 floats 2..7  (6 x shfl_up 1)
//   w14..w19 = lane t+1 floats 0..5  (6 x shfl_down 1)
// Lanes 0/31 patch from global (L2-hot); row ends symmetric-reflect.

#define ROW_L    4096
#define NTHREADS 256
#define NF8      (ROW_L / 8)     // 512 float8 per row
#define NF4      (ROW_L / 4)

struct F8 { float v[8]; };

__device__ __forceinline__ F8 ldg256(const float* p) {
    F8 r;
    asm("ld.global.nc.v8.f32 {%0,%1,%2,%3,%4,%5,%6,%7}, [%8];"
        : "=f"(r.v[0]), "=f"(r.v[1]), "=f"(r.v[2]), "=f"(r.v[3]),
          "=f"(r.v[4]), "=f"(r.v[5]), "=f"(r.v[6]), "=f"(r.v[7])
        : "l"(p));
    return r;
}

__device__ __forceinline__ void stg256(float* p,
                                       float a0, float a1, float a2, float a3,
                                       float a4, float a5, float a6, float a7) {
    asm volatile("st.global.v8.f32 [%0], {%1,%2,%3,%4,%5,%6,%7,%8};"
        :: "l"(p), "f"(a0), "f"(a1), "f"(a2), "f"(a3),
           "f"(a4), "f"(a5), "f"(a6), "f"(a7)
        : "memory");
}

__global__ void __launch_bounds__(NTHREADS)
dwt_db4_kernel(const float* __restrict__ x,
               float* __restrict__ low_out,
               float* __restrict__ high_out)
{
    const float h0 = -0.010597401784997278f;
    const float h1 =  0.032883011666982945f;
    const float h2 =  0.030841381835986965f;
    const float h3 = -0.18703481171888114f;
    const float h4 = -0.02798376941698385f;
    const float h5 =  0.6308807679295904f;
    const float h6 =  0.7148465705525415f;
    const float h7 =  0.23037781330885523f;

    const int t = threadIdx.x;
    const int l = t & 31;
    const size_t row = blockIdx.x;
    const float*  __restrict__ xr  = x + row * (size_t)ROW_L;
    const float4* __restrict__ xr4 = (const float4*)xr;
    float* __restrict__ lowp  = low_out  + row * (size_t)ROW_L;
    float* __restrict__ highp = high_out + row * (size_t)ROW_L;

    // Front-batched main loads: 2 x LDG.256 (64B per thread in flight)
    F8 va[2];
    #pragma unroll
    for (int g = 0; g < 2; ++g)
        va[g] = ldg256(xr + (size_t)(g * NTHREADS + t) * 8);

    #pragma unroll
    for (int g = 0; g < 2; ++g) {
        const int E = g * NTHREADS + t;      // float8 index in row, 0..511
        const F8 v = va[g];

        // Edge-patch loads FIRST (predicated, lanes 0/31 only): their L2
        // latency overlaps the 12 shuffles below.
        float4 PA, PB;
        bool refl_lo = false, refl_hi = false;
        if (l == 0) {
            refl_lo = (E == 0);
            PA = xr4[refl_lo ? 1 : 2 * E - 2];
            PB = xr4[refl_lo ? 0 : 2 * E - 1];
        }
        if (l == 31) {
            refl_hi = (E == NF8 - 1);
            PA = xr4[refl_hi ? (NF4 - 1) : 2 * E + 2];
            PB = xr4[refl_hi ? (NF4 - 2) : 2 * E + 3];
        }

        // window w[i] = X(8E - 6 + i), i = 0..19
        float w0, w1, w2, w3, w4, w5;
        const float w6 = v.v[0], w7 = v.v[1], w8 = v.v[2], w9 = v.v[3];
        const float w10 = v.v[4], w11 = v.v[5], w12 = v.v[6], w13 = v.v[7];
        float w14, w15, w16, w17, w18, w19;

        // halos via distance-1 shuffle (full-warp convergent)
        w0  = __shfl_up_sync(0xffffffffu, v.v[2], 1);
        w1  = __shfl_up_sync(0xffffffffu, v.v[3], 1);
        w2  = __shfl_up_sync(0xffffffffu, v.v[4], 1);
        w3  = __shfl_up_sync(0xffffffffu, v.v[5], 1);
        w4  = __shfl_up_sync(0xffffffffu, v.v[6], 1);
        w5  = __shfl_up_sync(0xffffffffu, v.v[7], 1);
        w14 = __shfl_down_sync(0xffffffffu, v.v[0], 1);
        w15 = __shfl_down_sync(0xffffffffu, v.v[1], 1);
        w16 = __shfl_down_sync(0xffffffffu, v.v[2], 1);
        w17 = __shfl_down_sync(0xffffffffu, v.v[3], 1);
        w18 = __shfl_down_sync(0xffffffffu, v.v[4], 1);
        w19 = __shfl_down_sync(0xffffffffu, v.v[5], 1);

        // apply pre-issued edge patches
        if (l == 0) {
            if (refl_lo) { w0 = PA.y; w1 = PA.x; w2 = PB.w; w3 = PB.z; w4 = PB.y; w5 = PB.x; }
            else         { w0 = PA.z; w1 = PA.w; w2 = PB.x; w3 = PB.y; w4 = PB.z; w5 = PB.w; }
        }
        if (l == 31) {
            if (refl_hi) { w14 = PA.w; w15 = PA.z; w16 = PA.y; w17 = PA.x; w18 = PB.w; w19 = PB.z; }
            else         { w14 = PA.x; w15 = PA.y; w16 = PA.z; w17 = PA.w; w18 = PB.x; w19 = PB.y; }
        }

        // analysis: ca[j] (global coeff index 4E + j), j = 0..6
        // ca_j = sum_m h[m] * w[2j + 7 - m]
        const float wv[20] = { w0, w1, w2, w3, w4, w5, w6, w7, w8, w9,
                               w10, w11, w12, w13, w14, w15, w16, w17, w18, w19 };
        float ca[7];
        #pragma unroll
        for (int j = 0; j < 7; ++j) {
            float s;
            s = h0 * wv[2 * j + 7];
            s = fmaf(h1, wv[2 * j + 6], s);
            s = fmaf(h2, wv[2 * j + 5], s);
            s = fmaf(h3, wv[2 * j + 4], s);
            s = fmaf(h4, wv[2 * j + 3], s);
            s = fmaf(h5, wv[2 * j + 2], s);
            s = fmaf(h6, wv[2 * j + 1], s);
            s = fmaf(h7, wv[2 * j + 0], s);
            ca[j] = s;
        }

        // synthesis: pairs p = 0..3 -> outputs x[8E .. 8E+7]
        float le[4], lo[4];
        #pragma unroll
        for (int p = 0; p < 4; ++p) {
            float e;
            e = h1 * ca[p];
            e = fmaf(h3, ca[p + 1], e);
            e = fmaf(h5, ca[p + 2], e);
            e = fmaf(h7, ca[p + 3], e);
            le[p] = e;

            float o;
            o = h0 * ca[p];
            o = fmaf(h2, ca[p + 1], o);
            o = fmaf(h4, ca[p + 2], o);
            o = fmaf(h6, ca[p + 3], o);
            lo[p] = o;
        }

        stg256(lowp + (size_t)E * 8,
               le[0], lo[0], le[1], lo[1], le[2], lo[2], le[3], lo[3]);
        stg256(highp + (size_t)E * 8,
               w6 - le[0], w7 - lo[0], w8 - le[1], w9 - lo[1],
               w10 - le[2], w11 - lo[2], w12 - le[3], w13 - lo[3]);
    }
}

extern "C" void kernel_launch(void* const* d_in, const int* in_sizes, int n_in,
                              void* d_out, int out_size)
{
    const float* x = (const float*)d_in[0];
    const int n = in_sizes[0];            // 16*512*4096
    float* low  = (float*)d_out;          // outputs concatenated: (low, high)
    float* high = low + (size_t)n;
    const int rows = n / ROW_L;           // 8192
    dwt_db4_kernel<<<rows, NTHREADS>>>(x, low, high);
}